// round 1
// baseline (speedup 1.0000x reference)
#include <cuda_runtime.h>
#include <cuda_bf16.h>

// Problem constants (fixed shapes per reference):
//   S=2048, B=1, D=1280, H=16, HD=80, NSEQ=8 (segments of <=256)
#define S_TOT   2048
#define D_MODEL 1280
#define THREE_D 3840
#define NHEAD   16
#define HDIM    80
#define MAXSEG  256
#define KSTRIDE 84   // K tile row stride in floats: 16B-aligned, LDS.128 phase-conflict-free

// Scratch for qkv = x @ W^T + b : [S, 3D] fp32 = 31.5 MB
__device__ float g_qkv[S_TOT * THREE_D];

// ---------------------------------------------------------------------------
// Kernel 1: QKV GEMM.  C[m,n] = sum_d X[m,d]*W[n,d] + bias[n]
// M=2048, N=3840, K=1280.  128x128 tile, BK=16, 256 threads, 8x8 microtile.
// ---------------------------------------------------------------------------
__global__ __launch_bounds__(256) void qkv_gemm_kernel(
    const float* __restrict__ X, const float* __restrict__ W,
    const float* __restrict__ bias)
{
    __shared__ float As[16][129];   // +1 pad: conflict-free transposed stores
    __shared__ float Bs[16][129];

    const int tid = threadIdx.x;
    const int tx  = tid & 15;       // 0..15 -> N microtile
    const int ty  = tid >> 4;       // 0..15 -> M microtile
    const int m0  = blockIdx.y * 128;
    const int n0  = blockIdx.x * 128;

    const int lr = tid >> 2;        // 0..63
    const int lc = (tid & 3) << 2;  // 0,4,8,12

    float acc[8][8];
#pragma unroll
    for (int i = 0; i < 8; i++)
#pragma unroll
        for (int j = 0; j < 8; j++) acc[i][j] = 0.0f;

    const float* Xp = X + (m0 + lr) * D_MODEL + lc;
    const float* Wp = W + (n0 + lr) * D_MODEL + lc;

    for (int k0 = 0; k0 < D_MODEL; k0 += 16) {
#pragma unroll
        for (int rr = 0; rr < 2; rr++) {
            const int r = lr + rr * 64;
            float4 av = *(const float4*)(Xp + rr * 64 * D_MODEL + k0);
            float4 bv = *(const float4*)(Wp + rr * 64 * D_MODEL + k0);
            As[lc + 0][r] = av.x; As[lc + 1][r] = av.y;
            As[lc + 2][r] = av.z; As[lc + 3][r] = av.w;
            Bs[lc + 0][r] = bv.x; Bs[lc + 1][r] = bv.y;
            Bs[lc + 2][r] = bv.z; Bs[lc + 3][r] = bv.w;
        }
        __syncthreads();
#pragma unroll
        for (int k = 0; k < 16; k++) {
            float a[8], b[8];
#pragma unroll
            for (int i = 0; i < 8; i++) a[i] = As[k][ty * 8 + i];
#pragma unroll
            for (int j = 0; j < 8; j++) b[j] = Bs[k][tx + 16 * j];  // strided: conflict-free
#pragma unroll
            for (int i = 0; i < 8; i++)
#pragma unroll
                for (int j = 0; j < 8; j++)
                    acc[i][j] = fmaf(a[i], b[j], acc[i][j]);
        }
        __syncthreads();
    }

    float bv[8];
#pragma unroll
    for (int j = 0; j < 8; j++) bv[j] = bias[n0 + tx + 16 * j];

#pragma unroll
    for (int i = 0; i < 8; i++) {
        const int m = m0 + ty * 8 + i;
        float* crow = g_qkv + (size_t)m * THREE_D + n0;
#pragma unroll
        for (int j = 0; j < 8; j++)
            crow[tx + 16 * j] = acc[i][j] + bv[j];
    }
}

// ---------------------------------------------------------------------------
// Kernel 2: block-diagonal attention.
// One CTA per (segment, head). 256 threads = 8 warps; warp w owns query rows
// [w*32, w*32+32), processed in groups of 4. K/V segment resident in SMEM.
// ---------------------------------------------------------------------------
#define ATTN_SMEM_FLOATS (256 * KSTRIDE + 256 * 80 + 8 * 4 * 256 + 8 * 4 * 80)
#define ATTN_SMEM_BYTES  (ATTN_SMEM_FLOATS * 4)

__global__ __launch_bounds__(256) void attn_kernel(
    const int* __restrict__ cu, float* __restrict__ out)
{
    const int seg = blockIdx.x;
    const int h   = blockIdx.y;
    const int s0  = cu[seg];
    const int L   = cu[seg + 1] - s0;   // segment length, <= 256
    const int tid = threadIdx.x;
    const int w    = tid >> 5;
    const int lane = tid & 31;

    extern __shared__ float sm[];
    float* Ks = sm;                      // [256][KSTRIDE]
    float* Vs = Ks + 256 * KSTRIDE;      // [256][80]
    float* ps = Vs + 256 * 80;           // [8 warps][4 rows][256]
    float* qb = ps + 8 * 4 * 256;        // [8 warps][4 rows][80]

    const float* QKV = g_qkv;

    // Load K,V segment (row-padded strides; zero the tail so masked-out keys
    // never inject NaN/Inf through 0 * garbage).
    for (int idx = tid; idx < L * 20; idx += 256) {
        const int t = idx / 20, c = (idx % 20) * 4;
        const float* base = QKV + (size_t)(s0 + t) * THREE_D + h * HDIM + c;
        *(float4*)&Ks[t * KSTRIDE + c] = *(const float4*)(base + D_MODEL);
        *(float4*)&Vs[t * 80 + c]      = *(const float4*)(base + 2 * D_MODEL);
    }
    for (int idx = tid + L * 20; idx < 256 * 20; idx += 256) {
        const int t = idx / 20, c = (idx % 20) * 4;
        *(float4*)&Ks[t * KSTRIDE + c] = make_float4(0.f, 0.f, 0.f, 0.f);
        *(float4*)&Vs[t * 80 + c]      = make_float4(0.f, 0.f, 0.f, 0.f);
    }
    __syncthreads();

    // exp(scale*(s-m)) = exp2(SCL2E*(s-m)),  scale = 1/sqrt(80)
    const float SCL2E = 0.11180339887498949f * 1.4426950408889634f;

    float* pw = ps + w * 4 * 256;
    float* qw = qb + w * 4 * 80;

    for (int rg = 0; rg < 8; rg++) {
        const int r0 = w * 32 + rg * 4;
        __syncwarp();
        // Stage 4 query rows into SMEM (broadcast-friendly)
        for (int idx = lane; idx < 80; idx += 32) {
            const int rr = idx / 20, c = (idx % 20) * 4;
            const int r = r0 + rr;
            float4 qv = make_float4(0.f, 0.f, 0.f, 0.f);
            if (r < L)
                qv = *(const float4*)(QKV + (size_t)(s0 + r) * THREE_D + h * HDIM + c);
            *(float4*)&qw[rr * 80 + c] = qv;
        }
        __syncwarp();

        // ---- scores: 4 rows x 8 keys-per-lane, K read as float4 ----
        float acc[4][8];
#pragma unroll
        for (int r = 0; r < 4; r++)
#pragma unroll
            for (int j = 0; j < 8; j++) acc[r][j] = 0.0f;

#pragma unroll 5
        for (int d4 = 0; d4 < 20; d4++) {
            float4 q0 = *(const float4*)&qw[0 * 80 + d4 * 4];
            float4 q1 = *(const float4*)&qw[1 * 80 + d4 * 4];
            float4 q2 = *(const float4*)&qw[2 * 80 + d4 * 4];
            float4 q3 = *(const float4*)&qw[3 * 80 + d4 * 4];
#pragma unroll
            for (int j = 0; j < 8; j++) {
                float4 kv = *(const float4*)&Ks[(j * 32 + lane) * KSTRIDE + d4 * 4];
                acc[0][j] = fmaf(q0.x, kv.x, fmaf(q0.y, kv.y, fmaf(q0.z, kv.z, fmaf(q0.w, kv.w, acc[0][j]))));
                acc[1][j] = fmaf(q1.x, kv.x, fmaf(q1.y, kv.y, fmaf(q1.z, kv.z, fmaf(q1.w, kv.w, acc[1][j]))));
                acc[2][j] = fmaf(q2.x, kv.x, fmaf(q2.y, kv.y, fmaf(q2.z, kv.z, fmaf(q2.w, kv.w, acc[2][j]))));
                acc[3][j] = fmaf(q3.x, kv.x, fmaf(q3.y, kv.y, fmaf(q3.z, kv.z, fmaf(q3.w, kv.w, acc[3][j]))));
            }
        }

        // ---- softmax (per row; key t = j*32+lane) ----
#pragma unroll
        for (int r = 0; r < 4; r++) {
            float m = -1e30f;
#pragma unroll
            for (int j = 0; j < 8; j++) {
                if (j * 32 + lane >= L) acc[r][j] = -1e30f;
                m = fmaxf(m, acc[r][j]);
            }
#pragma unroll
            for (int off = 16; off; off >>= 1)
                m = fmaxf(m, __shfl_xor_sync(0xffffffffu, m, off));
            float e[8], sum = 0.f;
#pragma unroll
            for (int j = 0; j < 8; j++) {
                e[j] = exp2f((acc[r][j] - m) * SCL2E);
                sum += e[j];
            }
#pragma unroll
            for (int off = 16; off; off >>= 1)
                sum += __shfl_xor_sync(0xffffffffu, sum, off);
            const float inv = 1.0f / sum;
#pragma unroll
            for (int j = 0; j < 8; j++)
                pw[r * 256 + j * 32 + lane] = e[j] * inv;
        }
        __syncwarp();

        // ---- output: lane < 20 owns hd dims [4*lane, 4*lane+4) ----
        if (lane < 20) {
            float4 o0 = make_float4(0.f,0.f,0.f,0.f), o1 = o0, o2 = o0, o3 = o0;
#pragma unroll 4
            for (int t = 0; t < 256; t++) {
                float4 vv = *(const float4*)&Vs[t * 80 + lane * 4];
                float p0 = pw[0 * 256 + t];
                float p1 = pw[1 * 256 + t];
                float p2 = pw[2 * 256 + t];
                float p3 = pw[3 * 256 + t];
                o0.x = fmaf(p0, vv.x, o0.x); o0.y = fmaf(p0, vv.y, o0.y);
                o0.z = fmaf(p0, vv.z, o0.z); o0.w = fmaf(p0, vv.w, o0.w);
                o1.x = fmaf(p1, vv.x, o1.x); o1.y = fmaf(p1, vv.y, o1.y);
                o1.z = fmaf(p1, vv.z, o1.z); o1.w = fmaf(p1, vv.w, o1.w);
                o2.x = fmaf(p2, vv.x, o2.x); o2.y = fmaf(p2, vv.y, o2.y);
                o2.z = fmaf(p2, vv.z, o2.z); o2.w = fmaf(p2, vv.w, o2.w);
                o3.x = fmaf(p3, vv.x, o3.x); o3.y = fmaf(p3, vv.y, o3.y);
                o3.z = fmaf(p3, vv.z, o3.z); o3.w = fmaf(p3, vv.w, o3.w);
            }
            // out layout: [b=1][s][h][hd] -> s*1280 + h*80 + hd
            float4 ov[4] = {o0, o1, o2, o3};
#pragma unroll
            for (int r = 0; r < 4; r++) {
                if (r0 + r < L) {
                    const int s = s0 + r0 + r;
                    *(float4*)&out[(size_t)s * (NHEAD * HDIM) + h * HDIM + lane * 4] = ov[r];
                }
            }
        }
    }
}

// ---------------------------------------------------------------------------
extern "C" void kernel_launch(void* const* d_in, const int* in_sizes, int n_in,
                              void* d_out, int out_size)
{
    const float* x    = (const float*)d_in[0];   // [2048,1,1280]
    const int*   cu   = (const int*)d_in[1];     // [9]
    const float* Wqkv = (const float*)d_in[2];   // [3840,1280]
    const float* bqkv = (const float*)d_in[3];   // [3840]
    float* out = (float*)d_out;                  // [1,2048,16,80]

    const int nseg = in_sizes[1] - 1;

    dim3 ggrid(THREE_D / 128, S_TOT / 128);      // (30, 16)
    qkv_gemm_kernel<<<ggrid, 256>>>(x, Wqkv, bqkv);

    cudaFuncSetAttribute(attn_kernel,
                         cudaFuncAttributeMaxDynamicSharedMemorySize,
                         ATTN_SMEM_BYTES);
    attn_kernel<<<dim3(nseg, NHEAD), 256, ATTN_SMEM_BYTES>>>(cu, out);
}

// round 3
// speedup vs baseline: 2.8297x; 2.8297x over previous
#include <cuda_runtime.h>
#include <cuda_bf16.h>
#include <cstdint>

// Problem constants: S=2048, B=1, D=1280, H=16, HD=80, NSEQ=8
#define S_TOT   2048
#define D_MODEL 1280
#define THREE_D 3840
#define NHEAD   16
#define HDIM    80
#define KSTRIDE 84

// Device scratch (no allocs allowed)
__device__ float g_qkv[S_TOT * THREE_D];              // qkv output, 31.5MB
__device__ float g_xt[S_TOT * D_MODEL];               // tf32-rounded X
__device__ float g_wt[THREE_D * D_MODEL];             // tf32-rounded W

// ============================ helpers ==================================
__device__ __forceinline__ uint32_t smem_u32(const void* p) {
    uint32_t a;
    asm("{ .reg .u64 t; cvta.to.shared.u64 t, %1; cvt.u32.u64 %0, t; }"
        : "=r"(a) : "l"(p));
    return a;
}
__device__ __forceinline__ uint32_t f2tf32(float f) {
    uint32_t u;
    asm("cvt.rna.tf32.f32 %0, %1;" : "=r"(u) : "f"(f));
    return u;
}
__device__ __forceinline__ void cp16(uint32_t dst, const void* src) {
    asm volatile("cp.async.ca.shared.global [%0], [%1], 16;"
                 :: "r"(dst), "l"(src));
}
#define CP_COMMIT() asm volatile("cp.async.commit_group;" ::: "memory")
#define CP_WAIT1()  asm volatile("cp.async.wait_group 1;" ::: "memory")

__device__ __forceinline__ void mma_tf32(float* d, const uint32_t* a,
                                         const uint32_t* b) {
    asm volatile(
        "mma.sync.aligned.m16n8k8.row.col.f32.tf32.tf32.f32 "
        "{%0,%1,%2,%3}, {%4,%5,%6,%7}, {%8,%9}, {%0,%1,%2,%3};"
        : "+f"(d[0]), "+f"(d[1]), "+f"(d[2]), "+f"(d[3])
        : "r"(a[0]), "r"(a[1]), "r"(a[2]), "r"(a[3]), "r"(b[0]), "r"(b[1]));
}

// ---------------------------------------------------------------------------
// Kernel 0: fp32 -> tf32 (round-to-nearest) pre-conversion
// ---------------------------------------------------------------------------
__global__ __launch_bounds__(256) void cvt_tf32_kernel(
    const float4* __restrict__ src, float4* __restrict__ dst, int n4)
{
    int i = blockIdx.x * 256 + threadIdx.x;
    if (i < n4) {
        float4 v = src[i];
        uint4 u = make_uint4(f2tf32(v.x), f2tf32(v.y), f2tf32(v.z), f2tf32(v.w));
        *(uint4*)&dst[i] = u;
    }
}

// ---------------------------------------------------------------------------
// Kernel 1: TF32 mma.sync QKV GEMM.  C[m,n] = sum_d X[m,d]*W[n,d] + bias[n]
// M=2048, N=3840, K=1280. CTA 128x256, BK=32, 3-stage cp.async pipeline.
// 8 warps (2 m x 4 n), warp tile 64x64 via m16n8k8.
// SMEM row stride 36 floats -> bank = (4*row + k) mod 32: conflict-free frags.
// ---------------------------------------------------------------------------
#define BK      32
#define KCHUNK  (D_MODEL / BK)          // 40
#define ASTRIDE 36
#define ASZF    (128 * ASTRIDE)         // 4608 floats
#define BSZF    (256 * ASTRIDE)         // 9216 floats
#define STAGEF  (ASZF + BSZF)           // 13824 floats
#define NSTAGE  3
#define GEMM_SMEM_BYTES (NSTAGE * STAGEF * 4)   // 165,888 B

__global__ __launch_bounds__(256) void qkv_gemm_mma(
    const float* __restrict__ bias)
{
    extern __shared__ float smf[];
    const uint32_t sb = smem_u32(smf);
    const int tid = threadIdx.x;
    const int wid = tid >> 5, lane = tid & 31;
    const int wm = wid & 1, wn = wid >> 1;      // 2 x 4 warp grid
    const int r  = lane >> 2, cq = lane & 3;
    const int m0 = blockIdx.y * 128;
    const int n0 = blockIdx.x * 256;

    const float* Xb = g_xt + (size_t)m0 * D_MODEL;
    const float* Wb = g_wt + (size_t)n0 * D_MODEL;

    // stage loader: 12 cp.async of 16B per thread
    auto issue = [&](int c, int s) {
        const int kk = c * BK;
        const uint32_t ab = sb + (uint32_t)(s * STAGEF) * 4u;
        const uint32_t bb = ab + (uint32_t)ASZF * 4u;
#pragma unroll
        for (int j = 0; j < 4; j++) {
            const int idx = tid + 256 * j;
            const int row = idx >> 3, kc = (idx & 7) << 2;
            cp16(ab + (uint32_t)(row * ASTRIDE + kc) * 4u,
                 Xb + (size_t)row * D_MODEL + kk + kc);
        }
#pragma unroll
        for (int j = 0; j < 8; j++) {
            const int idx = tid + 256 * j;
            const int row = idx >> 3, kc = (idx & 7) << 2;
            cp16(bb + (uint32_t)(row * ASTRIDE + kc) * 4u,
                 Wb + (size_t)row * D_MODEL + kk + kc);
        }
    };

    float acc[4][8][4];
#pragma unroll
    for (int mi = 0; mi < 4; mi++)
#pragma unroll
        for (int ni = 0; ni < 8; ni++)
#pragma unroll
            for (int q = 0; q < 4; q++) acc[mi][ni][q] = 0.0f;

    issue(0, 0); CP_COMMIT();
    issue(1, 1); CP_COMMIT();

    for (int c = 0; c < KCHUNK; c++) {
        const int s = c % NSTAGE;
        CP_WAIT1();
        __syncthreads();

        if (c + 2 < KCHUNK) issue(c + 2, (c + 2) % NSTAGE);
        CP_COMMIT();

        const uint32_t* Sa = (const uint32_t*)smf + s * STAGEF
                             + (wm * 64 + r) * ASTRIDE + cq;
        const uint32_t* Sb2 = (const uint32_t*)smf + s * STAGEF + ASZF
                              + (wn * 64 + r) * ASTRIDE + cq;
#pragma unroll
        for (int ks = 0; ks < 4; ks++) {
            uint32_t a[4][4], b[8][2];
            const int ko = ks * 8;
#pragma unroll
            for (int mi = 0; mi < 4; mi++) {
                a[mi][0] = Sa[(mi * 16 + 0) * ASTRIDE + ko];
                a[mi][1] = Sa[(mi * 16 + 8) * ASTRIDE + ko];
                a[mi][2] = Sa[(mi * 16 + 0) * ASTRIDE + ko + 4];
                a[mi][3] = Sa[(mi * 16 + 8) * ASTRIDE + ko + 4];
            }
#pragma unroll
            for (int ni = 0; ni < 8; ni++) {
                b[ni][0] = Sb2[ni * 8 * ASTRIDE + ko];
                b[ni][1] = Sb2[ni * 8 * ASTRIDE + ko + 4];
            }
#pragma unroll
            for (int mi = 0; mi < 4; mi++)
#pragma unroll
                for (int ni = 0; ni < 8; ni++)
                    mma_tf32(acc[mi][ni], a[mi], b[ni]);
        }
    }

    // Epilogue: bias + store (C frag: rows r,r+8; cols 2*cq, 2*cq+1)
    float bb[8][2];
#pragma unroll
    for (int ni = 0; ni < 8; ni++) {
        const int ncol = n0 + wn * 64 + ni * 8 + cq * 2;
        bb[ni][0] = bias[ncol];
        bb[ni][1] = bias[ncol + 1];
    }
#pragma unroll
    for (int mi = 0; mi < 4; mi++) {
        const int row0 = m0 + wm * 64 + mi * 16 + r;
#pragma unroll
        for (int ni = 0; ni < 8; ni++) {
            const int ncol = n0 + wn * 64 + ni * 8 + cq * 2;
            float2 v0 = make_float2(acc[mi][ni][0] + bb[ni][0],
                                    acc[mi][ni][1] + bb[ni][1]);
            float2 v1 = make_float2(acc[mi][ni][2] + bb[ni][0],
                                    acc[mi][ni][3] + bb[ni][1]);
            *(float2*)&g_qkv[(size_t)row0 * THREE_D + ncol] = v0;
            *(float2*)&g_qkv[(size_t)(row0 + 8) * THREE_D + ncol] = v1;
        }
    }
}

// ---------------------------------------------------------------------------
// Kernel 2: block-diagonal attention (unchanged from R1; 128us, known-good).
// ---------------------------------------------------------------------------
#define ATTN_SMEM_FLOATS (256 * KSTRIDE + 256 * 80 + 8 * 4 * 256 + 8 * 4 * 80)
#define ATTN_SMEM_BYTES  (ATTN_SMEM_FLOATS * 4)

__global__ __launch_bounds__(256) void attn_kernel(
    const int* __restrict__ cu, float* __restrict__ out)
{
    const int seg = blockIdx.x;
    const int h   = blockIdx.y;
    const int s0  = cu[seg];
    const int L   = cu[seg + 1] - s0;
    const int tid = threadIdx.x;
    const int w    = tid >> 5;
    const int lane = tid & 31;

    extern __shared__ float sm[];
    float* Ks = sm;
    float* Vs = Ks + 256 * KSTRIDE;
    float* ps = Vs + 256 * 80;
    float* qb = ps + 8 * 4 * 256;

    const float* QKV = g_qkv;

    for (int idx = tid; idx < L * 20; idx += 256) {
        const int t = idx / 20, c = (idx % 20) * 4;
        const float* base = QKV + (size_t)(s0 + t) * THREE_D + h * HDIM + c;
        *(float4*)&Ks[t * KSTRIDE + c] = *(const float4*)(base + D_MODEL);
        *(float4*)&Vs[t * 80 + c]      = *(const float4*)(base + 2 * D_MODEL);
    }
    for (int idx = tid + L * 20; idx < 256 * 20; idx += 256) {
        const int t = idx / 20, c = (idx % 20) * 4;
        *(float4*)&Ks[t * KSTRIDE + c] = make_float4(0.f, 0.f, 0.f, 0.f);
        *(float4*)&Vs[t * 80 + c]      = make_float4(0.f, 0.f, 0.f, 0.f);
    }
    __syncthreads();

    const float SCL2E = 0.11180339887498949f * 1.4426950408889634f;

    float* pw = ps + w * 4 * 256;
    float* qw = qb + w * 4 * 80;

    for (int rg = 0; rg < 8; rg++) {
        const int r0 = w * 32 + rg * 4;
        __syncwarp();
        for (int idx = lane; idx < 80; idx += 32) {
            const int rr = idx / 20, c = (idx % 20) * 4;
            const int r = r0 + rr;
            float4 qv = make_float4(0.f, 0.f, 0.f, 0.f);
            if (r < L)
                qv = *(const float4*)(QKV + (size_t)(s0 + r) * THREE_D + h * HDIM + c);
            *(float4*)&qw[rr * 80 + c] = qv;
        }
        __syncwarp();

        float acc[4][8];
#pragma unroll
        for (int r = 0; r < 4; r++)
#pragma unroll
            for (int j = 0; j < 8; j++) acc[r][j] = 0.0f;

#pragma unroll 5
        for (int d4 = 0; d4 < 20; d4++) {
            float4 q0 = *(const float4*)&qw[0 * 80 + d4 * 4];
            float4 q1 = *(const float4*)&qw[1 * 80 + d4 * 4];
            float4 q2 = *(const float4*)&qw[2 * 80 + d4 * 4];
            float4 q3 = *(const float4*)&qw[3 * 80 + d4 * 4];
#pragma unroll
            for (int j = 0; j < 8; j++) {
                float4 kv = *(const float4*)&Ks[(j * 32 + lane) * KSTRIDE + d4 * 4];
                acc[0][j] = fmaf(q0.x, kv.x, fmaf(q0.y, kv.y, fmaf(q0.z, kv.z, fmaf(q0.w, kv.w, acc[0][j]))));
                acc[1][j] = fmaf(q1.x, kv.x, fmaf(q1.y, kv.y, fmaf(q1.z, kv.z, fmaf(q1.w, kv.w, acc[1][j]))));
                acc[2][j] = fmaf(q2.x, kv.x, fmaf(q2.y, kv.y, fmaf(q2.z, kv.z, fmaf(q2.w, kv.w, acc[2][j]))));
                acc[3][j] = fmaf(q3.x, kv.x, fmaf(q3.y, kv.y, fmaf(q3.z, kv.z, fmaf(q3.w, kv.w, acc[3][j]))));
            }
        }

#pragma unroll
        for (int r = 0; r < 4; r++) {
            float m = -1e30f;
#pragma unroll
            for (int j = 0; j < 8; j++) {
                if (j * 32 + lane >= L) acc[r][j] = -1e30f;
                m = fmaxf(m, acc[r][j]);
            }
#pragma unroll
            for (int off = 16; off; off >>= 1)
                m = fmaxf(m, __shfl_xor_sync(0xffffffffu, m, off));
            float e[8], sum = 0.f;
#pragma unroll
            for (int j = 0; j < 8; j++) {
                e[j] = exp2f((acc[r][j] - m) * SCL2E);
                sum += e[j];
            }
#pragma unroll
            for (int off = 16; off; off >>= 1)
                sum += __shfl_xor_sync(0xffffffffu, sum, off);
            const float inv = 1.0f / sum;
#pragma unroll
            for (int j = 0; j < 8; j++)
                pw[r * 256 + j * 32 + lane] = e[j] * inv;
        }
        __syncwarp();

        if (lane < 20) {
            float4 o0 = make_float4(0.f,0.f,0.f,0.f), o1 = o0, o2 = o0, o3 = o0;
#pragma unroll 4
            for (int t = 0; t < 256; t++) {
                float4 vv = *(const float4*)&Vs[t * 80 + lane * 4];
                float p0 = pw[0 * 256 + t];
                float p1 = pw[1 * 256 + t];
                float p2 = pw[2 * 256 + t];
                float p3 = pw[3 * 256 + t];
                o0.x = fmaf(p0, vv.x, o0.x); o0.y = fmaf(p0, vv.y, o0.y);
                o0.z = fmaf(p0, vv.z, o0.z); o0.w = fmaf(p0, vv.w, o0.w);
                o1.x = fmaf(p1, vv.x, o1.x); o1.y = fmaf(p1, vv.y, o1.y);
                o1.z = fmaf(p1, vv.z, o1.z); o1.w = fmaf(p1, vv.w, o1.w);
                o2.x = fmaf(p2, vv.x, o2.x); o2.y = fmaf(p2, vv.y, o2.y);
                o2.z = fmaf(p2, vv.z, o2.z); o2.w = fmaf(p2, vv.w, o2.w);
                o3.x = fmaf(p3, vv.x, o3.x); o3.y = fmaf(p3, vv.y, o3.y);
                o3.z = fmaf(p3, vv.z, o3.z); o3.w = fmaf(p3, vv.w, o3.w);
            }
            float4 ov[4] = {o0, o1, o2, o3};
#pragma unroll
            for (int r = 0; r < 4; r++) {
                if (r0 + r < L) {
                    const int s = s0 + r0 + r;
                    *(float4*)&out[(size_t)s * (NHEAD * HDIM) + h * HDIM + lane * 4] = ov[r];
                }
            }
        }
    }
}

// ---------------------------------------------------------------------------
extern "C" void kernel_launch(void* const* d_in, const int* in_sizes, int n_in,
                              void* d_out, int out_size)
{
    const float* x    = (const float*)d_in[0];   // [2048,1,1280]
    const int*   cu   = (const int*)d_in[1];     // [9]
    const float* Wqkv = (const float*)d_in[2];   // [3840,1280]
    const float* bqkv = (const float*)d_in[3];   // [3840]
    float* out = (float*)d_out;                  // [1,2048,16,80]

    const int nseg = in_sizes[1] - 1;

    // Resolve device-global scratch addresses (host side, no allocation)
    float *xt_p, *wt_p;
    cudaGetSymbolAddress((void**)&xt_p, g_xt);
    cudaGetSymbolAddress((void**)&wt_p, g_wt);

    // tf32 pre-conversion
    const int n4x = S_TOT * D_MODEL / 4;         // 655360
    const int n4w = THREE_D * D_MODEL / 4;       // 1228800
    cvt_tf32_kernel<<<(n4x + 255) / 256, 256>>>((const float4*)x, (float4*)xt_p, n4x);
    cvt_tf32_kernel<<<(n4w + 255) / 256, 256>>>((const float4*)Wqkv, (float4*)wt_p, n4w);

    cudaFuncSetAttribute(qkv_gemm_mma,
                         cudaFuncAttributeMaxDynamicSharedMemorySize,
                         GEMM_SMEM_BYTES);
    dim3 ggrid(THREE_D / 256, S_TOT / 128);      // (15, 16)
    qkv_gemm_mma<<<ggrid, 256, GEMM_SMEM_BYTES>>>(bqkv);

    cudaFuncSetAttribute(attn_kernel,
                         cudaFuncAttributeMaxDynamicSharedMemorySize,
                         ATTN_SMEM_BYTES);
    attn_kernel<<<dim3(nseg, NHEAD), 256, ATTN_SMEM_BYTES>>>(cu, out);
}